// round 4
// baseline (speedup 1.0000x reference)
#include <cuda_runtime.h>
#include <math.h>

// Problem constants
#define B_N   4
#define H_N   16
#define S_N   2048
#define DM_N  1024
#define DH_N  64
#define M_N   (B_N * S_N)   // 8192

// Scratch (no cudaMalloc allowed) — ~134 MB total
__device__ float g_Q[(size_t)B_N * H_N * S_N * DH_N];   // [B,H,S,64]
__device__ float g_K[(size_t)B_N * H_N * S_N * DH_N];
__device__ float g_V[(size_t)B_N * H_N * S_N * DH_N];
__device__ float g_A[(size_t)M_N * DM_N];               // attn out, [B*S, 1024]

// ---------------------------------------------------------------------------
// GEMM: out = X[M,1024] @ W[1024,1024] + bias
// 64x64 tile, BK=16, 256 threads, 4x4 microtile.
// HEAD_LAYOUT=true scatters the output into [B,H,S,64] (head-major) layout.
// ---------------------------------------------------------------------------
template <bool HEAD_LAYOUT>
__global__ __launch_bounds__(256)
void gemm_bias_kernel(const float* __restrict__ X, const float* __restrict__ W,
                      const float* __restrict__ bias, float* __restrict__ out)
{
    __shared__ __align__(16) float As[16][68];  // k-major (transposed) A tile
    __shared__ __align__(16) float Bs[16][68];  // k-major B tile

    const int tid = threadIdx.x;
    const int tx = tid & 15, ty = tid >> 4;
    const int m0 = blockIdx.y << 6;
    const int n0 = blockIdx.x << 6;

    const int arow = tid >> 2;            // 0..63
    const int acol = (tid & 3) << 2;      // 0,4,8,12
    const int brow = tid >> 4;            // 0..15
    const int bcol = (tid & 15) << 2;     // 0..60

    const float* xp = X + (size_t)(m0 + arow) * DM_N + acol;
    const float* wp = W + (size_t)brow * DM_N + n0 + bcol;

    float acc[4][4] = {};

    for (int k0 = 0; k0 < DM_N; k0 += 16) {
        float4 av = *(const float4*)(xp + k0);
        float4 bv = *(const float4*)(wp + (size_t)k0 * DM_N);
        __syncthreads();
        As[acol + 0][arow] = av.x;
        As[acol + 1][arow] = av.y;
        As[acol + 2][arow] = av.z;
        As[acol + 3][arow] = av.w;
        *(float4*)&Bs[brow][bcol] = bv;
        __syncthreads();
#pragma unroll
        for (int kk = 0; kk < 16; kk++) {
            float4 a = *(const float4*)&As[kk][ty << 2];
            float4 b = *(const float4*)&Bs[kk][tx << 2];
            float ar[4] = {a.x, a.y, a.z, a.w};
            float br[4] = {b.x, b.y, b.z, b.w};
#pragma unroll
            for (int i = 0; i < 4; i++)
#pragma unroll
                for (int j = 0; j < 4; j++)
                    acc[i][j] += ar[i] * br[j];
        }
    }

#pragma unroll
    for (int j = 0; j < 4; j++) {
        const int n = n0 + (tx << 2) + j;
        const float bb = bias[n];
#pragma unroll
        for (int i = 0; i < 4; i++) {
            const int m = m0 + (ty << 2) + i;
            const float v = acc[i][j] + bb;
            if (HEAD_LAYOUT) {
                const int h = n >> 6, d = n & 63;
                const int bi = m >> 11, s = m & (S_N - 1);
                out[(((size_t)(bi * H_N + h)) * S_N + s) * DH_N + d] = v;
            } else {
                out[(size_t)m * DM_N + n] = v;
            }
        }
    }
}

// ---------------------------------------------------------------------------
// Flash-attention style kernel: one block = one (b,h) pair x 64 query rows.
// Loops over 32 key tiles of 64, online softmax.
// Dynamic smem: Qt[64][68] + Kt[64][68] + Vs[64][64] + Ss[64][65] + stats.
// ---------------------------------------------------------------------------
#define ATTN_SMEM_FLOATS (64*68 + 64*68 + 64*64 + 64*65 + 64 + 64 + 64 + 64*4)
#define ATTN_SMEM_BYTES  (ATTN_SMEM_FLOATS * 4)

__global__ __launch_bounds__(256)
void attn_kernel(const float* __restrict__ Q, const float* __restrict__ K,
                 const float* __restrict__ V, float* __restrict__ Aout)
{
    extern __shared__ __align__(16) float sm[];
    float* Qt  = sm;                 // [64 d][68]  depth-major Q
    float* Kt  = Qt + 64 * 68;       // [64 d][68]  depth-major K
    float* Vs  = Kt + 64 * 68;       // [64 c][64]  natural V
    float* Ss  = Vs + 64 * 64;       // [64 r][65]  scores / probs
    float* mS  = Ss + 64 * 65;       // [64] running max
    float* lS  = mS + 64;            // [64] running denom
    float* aS  = lS + 64;            // [64] rescale alpha
    float* red = aS + 64;            // [64][4] partial reductions

    const int tid = threadIdx.x;
    const int tx = tid & 15, ty = tid >> 4;
    const int bh = blockIdx.y;            // b*16 + h
    const int q0 = blockIdx.x << 6;

    const int lr = tid >> 2;              // 0..63  load/softmax row
    const int lp = tid & 3;               // 0..3   part
    const int dbase = lp << 4;            // 16-wide column slice

    // Load Q tile (transposed into depth-major)
    {
        const float* qbase = Q + ((size_t)bh * S_N + q0 + lr) * DH_N;
#pragma unroll
        for (int u = 0; u < 16; u += 4) {
            float4 v = *(const float4*)(qbase + dbase + u);
            Qt[(dbase + u + 0) * 68 + lr] = v.x;
            Qt[(dbase + u + 1) * 68 + lr] = v.y;
            Qt[(dbase + u + 2) * 68 + lr] = v.z;
            Qt[(dbase + u + 3) * 68 + lr] = v.w;
        }
    }
    if (lp == 0) { mS[lr] = -INFINITY; lS[lr] = 0.0f; }

    float oacc[4][4] = {};
    const float scale = 0.125f;  // 1/sqrt(64)

    for (int kt = 0; kt < S_N / 64; kt++) {
        const int k0 = kt << 6;
        __syncthreads();  // prior iteration done with Kt/Vs/Ss

        // Load K (transposed) and V (natural)
        {
            const float* kbase = K + ((size_t)bh * S_N + k0 + lr) * DH_N;
            const float* vbase = V + ((size_t)bh * S_N + k0 + lr) * DH_N;
#pragma unroll
            for (int u = 0; u < 16; u += 4) {
                float4 kv = *(const float4*)(kbase + dbase + u);
                Kt[(dbase + u + 0) * 68 + lr] = kv.x;
                Kt[(dbase + u + 1) * 68 + lr] = kv.y;
                Kt[(dbase + u + 2) * 68 + lr] = kv.z;
                Kt[(dbase + u + 3) * 68 + lr] = kv.w;
                float4 vv = *(const float4*)(vbase + dbase + u);
                *(float4*)&Vs[lr * 64 + dbase + u] = vv;
            }
        }
        __syncthreads();

        // S = Q @ K^T  (4x4 microtile per thread)
        float sacc[4][4] = {};
#pragma unroll 8
        for (int d = 0; d < 64; d++) {
            float4 a = *(const float4*)&Qt[d * 68 + (ty << 2)];
            float4 b = *(const float4*)&Kt[d * 68 + (tx << 2)];
            float ar[4] = {a.x, a.y, a.z, a.w};
            float br[4] = {b.x, b.y, b.z, b.w};
#pragma unroll
            for (int i = 0; i < 4; i++)
#pragma unroll
                for (int j = 0; j < 4; j++)
                    sacc[i][j] += ar[i] * br[j];
        }
#pragma unroll
        for (int i = 0; i < 4; i++)
#pragma unroll
            for (int j = 0; j < 4; j++)
                Ss[((ty << 2) + i) * 65 + (tx << 2) + j] = sacc[i][j] * scale;
        __syncthreads();

        // Online softmax: 4 threads per row
        float lmax = -INFINITY;
#pragma unroll
        for (int j = 0; j < 16; j++)
            lmax = fmaxf(lmax, Ss[lr * 65 + dbase + j]);
        red[(lr << 2) + lp] = lmax;
        __syncthreads();
        if (lp == 0) {
            float rm = fmaxf(fmaxf(red[lr << 2], red[(lr << 2) + 1]),
                             fmaxf(red[(lr << 2) + 2], red[(lr << 2) + 3]));
            float mo = mS[lr];
            float nm = fmaxf(mo, rm);
            aS[lr] = __expf(mo - nm);
            mS[lr] = nm;
        }
        __syncthreads();
        {
            const float nm = mS[lr];
            float ls = 0.0f;
#pragma unroll
            for (int j = 0; j < 16; j++) {
                float p = __expf(Ss[lr * 65 + dbase + j] - nm);
                Ss[lr * 65 + dbase + j] = p;
                ls += p;
            }
            red[(lr << 2) + lp] = ls;
        }
        // Rescale accumulated O by alpha (aS valid since last sync)
#pragma unroll
        for (int i = 0; i < 4; i++) {
            const float al = aS[(ty << 2) + i];
#pragma unroll
            for (int j = 0; j < 4; j++) oacc[i][j] *= al;
        }
        __syncthreads();
        if (lp == 0) {
            lS[lr] = lS[lr] * aS[lr] + red[lr << 2] + red[(lr << 2) + 1]
                   + red[(lr << 2) + 2] + red[(lr << 2) + 3];
        }

        // O += P @ V
#pragma unroll 8
        for (int c = 0; c < 64; c++) {
            float pr[4];
#pragma unroll
            for (int i = 0; i < 4; i++)
                pr[i] = Ss[((ty << 2) + i) * 65 + c];
            float4 v = *(const float4*)&Vs[c * 64 + (tx << 2)];
            float vr[4] = {v.x, v.y, v.z, v.w};
#pragma unroll
            for (int i = 0; i < 4; i++)
#pragma unroll
                for (int j = 0; j < 4; j++)
                    oacc[i][j] += pr[i] * vr[j];
        }
    }
    __syncthreads();

    // Epilogue: normalize and write to [B,S,1024] scratch
    const int b = bh >> 4, h = bh & 15;
#pragma unroll
    for (int i = 0; i < 4; i++) {
        const int r = (ty << 2) + i;
        const float inv = 1.0f / lS[r];
        const int s = q0 + r;
        float* op = Aout + ((size_t)(b * S_N) + s) * DM_N + (h << 6) + (tx << 2);
#pragma unroll
        for (int j = 0; j < 4; j++)
            op[j] = oacc[i][j] * inv;
    }
}

// ---------------------------------------------------------------------------
// Launch: 3 projections -> attention -> output projection (same stream).
// ---------------------------------------------------------------------------
extern "C" void kernel_launch(void* const* d_in, const int* in_sizes, int n_in,
                              void* d_out, int out_size)
{
    const float* v  = (const float*)d_in[0];
    const float* k  = (const float*)d_in[1];
    const float* q  = (const float*)d_in[2];
    const float* wq = (const float*)d_in[3];
    const float* bq = (const float*)d_in[4];
    const float* wk = (const float*)d_in[5];
    const float* bk = (const float*)d_in[6];
    const float* wv = (const float*)d_in[7];
    const float* bv = (const float*)d_in[8];
    const float* wo = (const float*)d_in[9];
    const float* bo = (const float*)d_in[10];
    float* out = (float*)d_out;

    float *pQ, *pK, *pV, *pA;
    cudaGetSymbolAddress((void**)&pQ, g_Q);
    cudaGetSymbolAddress((void**)&pK, g_K);
    cudaGetSymbolAddress((void**)&pV, g_V);
    cudaGetSymbolAddress((void**)&pA, g_A);

    cudaFuncSetAttribute(attn_kernel,
                         cudaFuncAttributeMaxDynamicSharedMemorySize,
                         ATTN_SMEM_BYTES);

    dim3 gg(DM_N / 64, M_N / 64);   // (16, 128)
    gemm_bias_kernel<true><<<gg, 256>>>(q, wq, bq, pQ);
    gemm_bias_kernel<true><<<gg, 256>>>(k, wk, bk, pK);
    gemm_bias_kernel<true><<<gg, 256>>>(v, wv, bv, pV);

    attn_kernel<<<dim3(S_N / 64, B_N * H_N), 256, ATTN_SMEM_BYTES>>>(pQ, pK, pV, pA);

    gemm_bias_kernel<false><<<gg, 256>>>(pA, wo, bo, out);
}

// round 6
// speedup vs baseline: 3.3850x; 3.3850x over previous
#include <cuda_runtime.h>
#include <math.h>

#define B_N   4
#define H_N   16
#define S_N   2048
#define DM_N  1024
#define M_N   (B_N * S_N)   // 8192

// Scratch (no cudaMalloc allowed)
__device__ float g_Q[(size_t)B_N * H_N * S_N * 64];
__device__ float g_K[(size_t)B_N * H_N * S_N * 64];
__device__ float g_V[(size_t)B_N * H_N * S_N * 64];
__device__ float g_A[(size_t)M_N * DM_N];

// ---------------------------------------------------------------------------
// tf32 mma.sync helpers
// ---------------------------------------------------------------------------
__device__ __forceinline__ float f2tff(float x) {
    unsigned r;
    asm("cvt.rna.tf32.f32 %0, %1;" : "=r"(r) : "f"(x));
    return __uint_as_float(r);
}
__device__ __forceinline__ unsigned sptr(const void* p) {
    return (unsigned)__cvta_generic_to_shared(p);
}
__device__ __forceinline__ void ldsm4(unsigned& r0, unsigned& r1,
                                      unsigned& r2, unsigned& r3, unsigned a) {
    asm volatile("ldmatrix.sync.aligned.m8n8.x4.shared.b16 {%0,%1,%2,%3}, [%4];"
                 : "=r"(r0), "=r"(r1), "=r"(r2), "=r"(r3) : "r"(a));
}
__device__ __forceinline__ void mma8(float* c, const unsigned* a, const unsigned* b) {
    asm volatile(
        "mma.sync.aligned.m16n8k8.row.col.f32.tf32.tf32.f32 "
        "{%0,%1,%2,%3}, {%4,%5,%6,%7}, {%8,%9}, {%0,%1,%2,%3};"
        : "+f"(c[0]), "+f"(c[1]), "+f"(c[2]), "+f"(c[3])
        : "r"(a[0]), "r"(a[1]), "r"(a[2]), "r"(a[3]), "r"(b[0]), "r"(b[1]));
}

// ---------------------------------------------------------------------------
// GEMM: out = X[M,1024] @ W[1024,1024] + bias   (tf32 tensor cores)
// CTA tile 128x128, BK=32, 256 threads (8 warps as 2m x 4n, warp = 64x32).
// Xs: [128][36] row-major padded (ldmatrix conflict-free: 144B row = 9 16B-banks)
// Ws: [128 n][32 k] with XOR chunk swizzle: float4 chunk c stored at c^(n&7).
// HEAD_LAYOUT scatters output into [B,H,S,64].
// ---------------------------------------------------------------------------
template <bool HL>
__global__ __launch_bounds__(256)
void gemm_tc(const float* __restrict__ X, const float* __restrict__ W,
             const float* __restrict__ bias, float* __restrict__ out)
{
    __shared__ __align__(16) float Xs[128 * 36];
    __shared__ __align__(16) float Ws[128 * 32];

    const int tid  = threadIdx.x;
    const int lane = tid & 31;
    const int wid  = tid >> 5;
    const int wm   = wid & 1;      // 0..1  (m direction, 64 rows each)
    const int wn   = wid >> 1;     // 0..3  (n direction, 32 cols each)
    const int m0   = blockIdx.y << 7;
    const int n0   = blockIdx.x << 7;

    float acc[4][4][4];
#pragma unroll
    for (int i = 0; i < 4; i++)
#pragma unroll
        for (int j = 0; j < 4; j++)
#pragma unroll
            for (int r = 0; r < 4; r++) acc[i][j][r] = 0.f;

    float4 xf[4];
    float  wf[4][4];

    // prefetch stage 0
#pragma unroll
    for (int u = 0; u < 4; u++) {
        int fid = u * 256 + tid;
        int r = fid >> 3, c4 = fid & 7;
        xf[u] = *(const float4*)(X + (size_t)(m0 + r) * DM_N + 4 * c4);
        int n = fid & 127, c = fid >> 7;
        const float* wp = W + (size_t)(4 * c) * DM_N + n0 + n;
#pragma unroll
        for (int i = 0; i < 4; i++) wf[u][i] = wp[(size_t)i * DM_N];
    }

    for (int k0 = 0; k0 < DM_N; k0 += 32) {
        __syncthreads();
        // store prefetched stage to smem (tf32-rounded)
#pragma unroll
        for (int u = 0; u < 4; u++) {
            int fid = u * 256 + tid;
            int r = fid >> 3, c4 = fid & 7;
            float4 v = xf[u];
            v.x = f2tff(v.x); v.y = f2tff(v.y); v.z = f2tff(v.z); v.w = f2tff(v.w);
            *(float4*)&Xs[r * 36 + 4 * c4] = v;
            int n = fid & 127, c = fid >> 7;
            float4 w4 = make_float4(f2tff(wf[u][0]), f2tff(wf[u][1]),
                                    f2tff(wf[u][2]), f2tff(wf[u][3]));
            *(float4*)&Ws[n * 32 + 4 * (c ^ (n & 7))] = w4;
        }
        __syncthreads();
        // issue next stage's global loads (latency hidden behind MMA)
        if (k0 + 32 < DM_N) {
#pragma unroll
            for (int u = 0; u < 4; u++) {
                int fid = u * 256 + tid;
                int r = fid >> 3, c4 = fid & 7;
                xf[u] = *(const float4*)(X + (size_t)(m0 + r) * DM_N + k0 + 32 + 4 * c4);
                int n = fid & 127, c = fid >> 7;
                const float* wp = W + (size_t)(k0 + 32 + 4 * c) * DM_N + n0 + n;
#pragma unroll
                for (int i = 0; i < 4; i++) wf[u][i] = wp[(size_t)i * DM_N];
            }
        }
        // 4 k8-steps of MMA
#pragma unroll
        for (int ks = 0; ks < 4; ks++) {
            const int kk = ks * 8;
            unsigned a[4][4], b[4][2];
#pragma unroll
            for (int mi = 0; mi < 4; mi++) {
                unsigned ad = sptr(&Xs[(wm * 64 + mi * 16 + (lane & 15)) * 36
                                       + kk + 4 * (lane >> 4)]);
                ldsm4(a[mi][0], a[mi][1], a[mi][2], a[mi][3], ad);
            }
#pragma unroll
            for (int p = 0; p < 2; p++) {
                int r  = wn * 32 + p * 16 + ((lane & 16) ? 8 : 0) + (lane & 7);
                int cc = (kk >> 2) + ((lane >> 3) & 1);
                unsigned ad = sptr(&Ws[r * 32 + 4 * (cc ^ (r & 7))]);
                unsigned t0, t1, t2, t3;
                ldsm4(t0, t1, t2, t3, ad);
                b[2 * p][0] = t0; b[2 * p][1] = t1;
                b[2 * p + 1][0] = t2; b[2 * p + 1][1] = t3;
            }
#pragma unroll
            for (int mi = 0; mi < 4; mi++)
#pragma unroll
                for (int nj = 0; nj < 4; nj++)
                    mma8(acc[mi][nj], a[mi], b[nj]);
        }
    }

    // epilogue
#pragma unroll
    for (int mi = 0; mi < 4; mi++) {
#pragma unroll
        for (int nj = 0; nj < 4; nj++) {
            int row = m0 + wm * 64 + mi * 16 + (lane >> 2);
            int col = n0 + wn * 32 + nj * 8 + 2 * (lane & 3);
            float b0v = bias[col], b1v = bias[col + 1];
            float2 v0 = make_float2(acc[mi][nj][0] + b0v, acc[mi][nj][1] + b1v);
            float2 v1 = make_float2(acc[mi][nj][2] + b0v, acc[mi][nj][3] + b1v);
            if (HL) {
                int h = col >> 6, d = col & 63;
                int bi = row >> 11, s = row & (S_N - 1);
                size_t base = (((size_t)(bi * H_N + h)) * S_N + s) * 64 + d;
                *(float2*)(out + base) = v0;
                *(float2*)(out + base + (size_t)8 * 64) = v1;   // row+8 same batch
            } else {
                float* p = out + (size_t)row * DM_N + col;
                *(float2*)p = v0;
                *(float2*)(p + (size_t)8 * DM_N) = v1;
            }
        }
    }
}

// ---------------------------------------------------------------------------
// Flash attention (tf32 tensor cores). Block = (b,h) x 128 q rows, 8 warps,
// each warp owns 16 q rows. 64-key tiles, online softmax fully in registers.
// Qs[128][68], Ks[64][68] (natural = B-layout for QK^T), Vt[64 d][68 key]
// (transposed = B-layout for PV), Ps[128][68] for P re-fragmentation.
// Pitch 68 floats = 17 16B-banks -> ldmatrix conflict-free.
// ---------------------------------------------------------------------------
#define ATTN_SMEM_BYTES ((128 + 64 + 64 + 128) * 68 * 4)

__global__ __launch_bounds__(256)
void attn_tc(const float* __restrict__ Q, const float* __restrict__ K,
             const float* __restrict__ V, float* __restrict__ O)
{
    extern __shared__ __align__(16) float sm[];
    float* Qs = sm;                 // 128*68
    float* Ks = Qs + 128 * 68;      // 64*68
    float* Vt = Ks + 64 * 68;       // 64*68
    float* Ps = Vt + 64 * 68;       // 128*68

    const int tid  = threadIdx.x;
    const int lane = tid & 31;
    const int wid  = tid >> 5;
    const int bh   = blockIdx.y;
    const int q0   = blockIdx.x << 7;

    const float* Qb = Q + ((size_t)bh * S_N + q0) * 64;
    const float* Kb = K + (size_t)bh * S_N * 64;
    const float* Vb = V + (size_t)bh * S_N * 64;

    // load Q once (tf32-rounded)
#pragma unroll
    for (int u = 0; u < 8; u++) {
        int fid = u * 256 + tid;
        int r = fid >> 4, c4 = fid & 15;
        float4 v = *(const float4*)(Qb + (size_t)r * 64 + 4 * c4);
        v.x = f2tff(v.x); v.y = f2tff(v.y); v.z = f2tff(v.z); v.w = f2tff(v.w);
        *(float4*)&Qs[r * 68 + 4 * c4] = v;
    }

    float accO[8][4];
#pragma unroll
    for (int j = 0; j < 8; j++)
#pragma unroll
        for (int r = 0; r < 4; r++) accO[j][r] = 0.f;
    float m0r = -INFINITY, m1r = -INFINITY, l0r = 0.f, l1r = 0.f;

    float4 kf[4], vf[4];
    // prefetch tile 0
#pragma unroll
    for (int u = 0; u < 4; u++) {
        int fid = u * 256 + tid;
        { int r = fid >> 4, c4 = fid & 15;
          kf[u] = *(const float4*)(Kb + (size_t)r * 64 + 4 * c4); }
        { int key = fid & 63, c4 = fid >> 6;
          vf[u] = *(const float4*)(Vb + (size_t)key * 64 + 4 * c4); }
    }

    for (int kt = 0; kt < S_N / 64; kt++) {
        __syncthreads();
        // store K natural, V transposed (lanes span 32 keys -> conflict-free)
#pragma unroll
        for (int u = 0; u < 4; u++) {
            int fid = u * 256 + tid;
            { int r = fid >> 4, c4 = fid & 15;
              float4 v = kf[u];
              v.x = f2tff(v.x); v.y = f2tff(v.y); v.z = f2tff(v.z); v.w = f2tff(v.w);
              *(float4*)&Ks[r * 68 + 4 * c4] = v; }
            { int key = fid & 63, c4 = fid >> 6;
              float4 v = vf[u];
              Vt[(4 * c4 + 0) * 68 + key] = f2tff(v.x);
              Vt[(4 * c4 + 1) * 68 + key] = f2tff(v.y);
              Vt[(4 * c4 + 2) * 68 + key] = f2tff(v.z);
              Vt[(4 * c4 + 3) * 68 + key] = f2tff(v.w); }
        }
        __syncthreads();
        // prefetch next tile
        if (kt + 1 < S_N / 64) {
            const float* Kb2 = Kb + (size_t)(kt + 1) * 64 * 64;
            const float* Vb2 = Vb + (size_t)(kt + 1) * 64 * 64;
#pragma unroll
            for (int u = 0; u < 4; u++) {
                int fid = u * 256 + tid;
                { int r = fid >> 4, c4 = fid & 15;
                  kf[u] = *(const float4*)(Kb2 + (size_t)r * 64 + 4 * c4); }
                { int key = fid & 63, c4 = fid >> 6;
                  vf[u] = *(const float4*)(Vb2 + (size_t)key * 64 + 4 * c4); }
            }
        }

        // S = Q @ K^T  (contraction over d=64)
        float accS[8][4];
#pragma unroll
        for (int j = 0; j < 8; j++)
#pragma unroll
            for (int r = 0; r < 4; r++) accS[j][r] = 0.f;
#pragma unroll
        for (int ks = 0; ks < 8; ks++) {
            const int kk = ks * 8;
            unsigned a[4], b[8][2];
            {
                unsigned ad = sptr(&Qs[(wid * 16 + (lane & 15)) * 68
                                       + kk + 4 * (lane >> 4)]);
                ldsm4(a[0], a[1], a[2], a[3], ad);
            }
#pragma unroll
            for (int p = 0; p < 4; p++) {
                int r = p * 16 + ((lane & 16) ? 8 : 0) + (lane & 7);
                unsigned ad = sptr(&Ks[r * 68 + kk + 4 * ((lane >> 3) & 1)]);
                unsigned t0, t1, t2, t3;
                ldsm4(t0, t1, t2, t3, ad);
                b[2 * p][0] = t0; b[2 * p][1] = t1;
                b[2 * p + 1][0] = t2; b[2 * p + 1][1] = t3;
            }
#pragma unroll
            for (int nj = 0; nj < 8; nj++) mma8(accS[nj], a, b[nj]);
        }

        // online softmax (rows t/4 and t/4+8; reduce across the 4-lane quad)
        float rmax0 = -INFINITY, rmax1 = -INFINITY;
#pragma unroll
        for (int j = 0; j < 8; j++) {
            accS[j][0] *= 0.125f; accS[j][1] *= 0.125f;
            accS[j][2] *= 0.125f; accS[j][3] *= 0.125f;
            rmax0 = fmaxf(rmax0, fmaxf(accS[j][0], accS[j][1]));
            rmax1 = fmaxf(rmax1, fmaxf(accS[j][2], accS[j][3]));
        }
        rmax0 = fmaxf(rmax0, __shfl_xor_sync(0xffffffffu, rmax0, 1));
        rmax0 = fmaxf(rmax0, __shfl_xor_sync(0xffffffffu, rmax0, 2));
        rmax1 = fmaxf(rmax1, __shfl_xor_sync(0xffffffffu, rmax1, 1));
        rmax1 = fmaxf(rmax1, __shfl_xor_sync(0xffffffffu, rmax1, 2));
        float mn0 = fmaxf(m0r, rmax0), mn1 = fmaxf(m1r, rmax1);
        float al0 = __expf(m0r - mn0), al1 = __expf(m1r - mn1);
        m0r = mn0; m1r = mn1;
        float s0 = 0.f, s1 = 0.f;
#pragma unroll
        for (int j = 0; j < 8; j++) {
            accS[j][0] = __expf(accS[j][0] - mn0);
            accS[j][1] = __expf(accS[j][1] - mn0);
            accS[j][2] = __expf(accS[j][2] - mn1);
            accS[j][3] = __expf(accS[j][3] - mn1);
            s0 += accS[j][0] + accS[j][1];
            s1 += accS[j][2] + accS[j][3];
        }
        s0 += __shfl_xor_sync(0xffffffffu, s0, 1);
        s0 += __shfl_xor_sync(0xffffffffu, s0, 2);
        s1 += __shfl_xor_sync(0xffffffffu, s1, 1);
        s1 += __shfl_xor_sync(0xffffffffu, s1, 2);
        l0r = l0r * al0 + s0;
        l1r = l1r * al1 + s1;
#pragma unroll
        for (int j = 0; j < 8; j++) {
            accO[j][0] *= al0; accO[j][1] *= al0;
            accO[j][2] *= al1; accO[j][3] *= al1;
        }

        // store P (tf32-rounded) to warp-private Ps rows
        {
            int pr = wid * 16 + (lane >> 2);
#pragma unroll
            for (int j = 0; j < 8; j++) {
                int c = j * 8 + 2 * (lane & 3);
                *(float2*)&Ps[pr * 68 + c] =
                    make_float2(f2tff(accS[j][0]), f2tff(accS[j][1]));
                *(float2*)&Ps[(pr + 8) * 68 + c] =
                    make_float2(f2tff(accS[j][2]), f2tff(accS[j][3]));
            }
        }
        __syncwarp();

        // O += P @ V  (contraction over 64 keys)
#pragma unroll
        for (int ks = 0; ks < 8; ks++) {
            const int kk = ks * 8;
            unsigned a[4], b[8][2];
            {
                unsigned ad = sptr(&Ps[(wid * 16 + (lane & 15)) * 68
                                       + kk + 4 * (lane >> 4)]);
                ldsm4(a[0], a[1], a[2], a[3], ad);
            }
#pragma unroll
            for (int p = 0; p < 4; p++) {
                int r = p * 16 + ((lane & 16) ? 8 : 0) + (lane & 7);
                unsigned ad = sptr(&Vt[r * 68 + kk + 4 * ((lane >> 3) & 1)]);
                unsigned t0, t1, t2, t3;
                ldsm4(t0, t1, t2, t3, ad);
                b[2 * p][0] = t0; b[2 * p][1] = t1;
                b[2 * p + 1][0] = t2; b[2 * p + 1][1] = t3;
            }
#pragma unroll
            for (int nj = 0; nj < 8; nj++) mma8(accO[nj], a, b[nj]);
        }
    }

    // epilogue: normalize, write to [B,S,1024] at head offset
    const float inv0 = 1.f / l0r, inv1 = 1.f / l1r;
    const int b = bh >> 4, h = bh & 15;
    const int r0 = q0 + wid * 16 + (lane >> 2);
#pragma unroll
    for (int j = 0; j < 8; j++) {
        int col = h * 64 + j * 8 + 2 * (lane & 3);
        float* p = O + ((size_t)b * S_N + r0) * DM_N + col;
        *(float2*)p = make_float2(accO[j][0] * inv0, accO[j][1] * inv0);
        *(float2*)(p + (size_t)8 * DM_N) =
            make_float2(accO[j][2] * inv1, accO[j][3] * inv1);
    }
}

// ---------------------------------------------------------------------------
// Launch
// ---------------------------------------------------------------------------
extern "C" void kernel_launch(void* const* d_in, const int* in_sizes, int n_in,
                              void* d_out, int out_size)
{
    const float* v  = (const float*)d_in[0];
    const float* k  = (const float*)d_in[1];
    const float* q  = (const float*)d_in[2];
    const float* wq = (const float*)d_in[3];
    const float* bq = (const float*)d_in[4];
    const float* wk = (const float*)d_in[5];
    const float* bk = (const float*)d_in[6];
    const float* wv = (const float*)d_in[7];
    const float* bv = (const float*)d_in[8];
    const float* wo = (const float*)d_in[9];
    const float* bo = (const float*)d_in[10];
    float* out = (float*)d_out;

    float *pQ, *pK, *pV, *pA;
    cudaGetSymbolAddress((void**)&pQ, g_Q);
    cudaGetSymbolAddress((void**)&pK, g_K);
    cudaGetSymbolAddress((void**)&pV, g_V);
    cudaGetSymbolAddress((void**)&pA, g_A);

    cudaFuncSetAttribute(attn_tc,
                         cudaFuncAttributeMaxDynamicSharedMemorySize,
                         ATTN_SMEM_BYTES);

    dim3 gg(DM_N / 128, M_N / 128);   // (8, 64)
    gemm_tc<true><<<gg, 256>>>(q, wq, bq, pQ);
    gemm_tc<true><<<gg, 256>>>(k, wk, bk, pK);
    gemm_tc<true><<<gg, 256>>>(v, wv, bv, pV);

    attn_tc<<<dim3(S_N / 128, B_N * H_N), 256, ATTN_SMEM_BYTES>>>(pQ, pK, pV, pA);

    gemm_tc<false><<<gg, 256>>>(pA, wo, bo, out);
}

// round 7
// speedup vs baseline: 3.9733x; 1.1738x over previous
#include <cuda_runtime.h>
#include <math.h>

#define B_N   4
#define H_N   16
#define S_N   2048
#define DM_N  1024
#define M_N   (B_N * S_N)   // 8192

// Scratch (no cudaMalloc allowed)
__device__ float g_Q[(size_t)B_N * H_N * S_N * 64];
__device__ float g_K[(size_t)B_N * H_N * S_N * 64];
__device__ float g_V[(size_t)B_N * H_N * S_N * 64];
__device__ float g_A[(size_t)M_N * DM_N];

// ---------------------------------------------------------------------------
// tf32 mma.sync helpers
// ---------------------------------------------------------------------------
__device__ __forceinline__ float f2tff(float x) {
    unsigned r;
    asm("cvt.rna.tf32.f32 %0, %1;" : "=r"(r) : "f"(x));
    return __uint_as_float(r);
}
__device__ __forceinline__ unsigned sptr(const void* p) {
    return (unsigned)__cvta_generic_to_shared(p);
}
__device__ __forceinline__ void ldsm4(unsigned& r0, unsigned& r1,
                                      unsigned& r2, unsigned& r3, unsigned a) {
    asm volatile("ldmatrix.sync.aligned.m8n8.x4.shared.b16 {%0,%1,%2,%3}, [%4];"
                 : "=r"(r0), "=r"(r1), "=r"(r2), "=r"(r3) : "r"(a));
}
__device__ __forceinline__ void mma8(float* c, const unsigned* a, const unsigned* b) {
    asm volatile(
        "mma.sync.aligned.m16n8k8.row.col.f32.tf32.tf32.f32 "
        "{%0,%1,%2,%3}, {%4,%5,%6,%7}, {%8,%9}, {%0,%1,%2,%3};"
        : "+f"(c[0]), "+f"(c[1]), "+f"(c[2]), "+f"(c[3])
        : "r"(a[0]), "r"(a[1]), "r"(a[2]), "r"(a[3]), "r"(b[0]), "r"(b[1]));
}

// ---------------------------------------------------------------------------
// GEMM: out = X[M,1024] @ W[1024,1024] + bias   (tf32 tensor cores)
// (unchanged from R6 — 128x128 tile, BK=32, 8 warps, reg-prefetch)
// ---------------------------------------------------------------------------
template <bool HL>
__global__ __launch_bounds__(256)
void gemm_tc(const float* __restrict__ X, const float* __restrict__ W,
             const float* __restrict__ bias, float* __restrict__ out)
{
    __shared__ __align__(16) float Xs[128 * 36];
    __shared__ __align__(16) float Ws[128 * 32];

    const int tid  = threadIdx.x;
    const int lane = tid & 31;
    const int wid  = tid >> 5;
    const int wm   = wid & 1;
    const int wn   = wid >> 1;
    const int m0   = blockIdx.y << 7;
    const int n0   = blockIdx.x << 7;

    float acc[4][4][4];
#pragma unroll
    for (int i = 0; i < 4; i++)
#pragma unroll
        for (int j = 0; j < 4; j++)
#pragma unroll
            for (int r = 0; r < 4; r++) acc[i][j][r] = 0.f;

    float4 xf[4];
    float  wf[4][4];

#pragma unroll
    for (int u = 0; u < 4; u++) {
        int fid = u * 256 + tid;
        int r = fid >> 3, c4 = fid & 7;
        xf[u] = *(const float4*)(X + (size_t)(m0 + r) * DM_N + 4 * c4);
        int n = fid & 127, c = fid >> 7;
        const float* wp = W + (size_t)(4 * c) * DM_N + n0 + n;
#pragma unroll
        for (int i = 0; i < 4; i++) wf[u][i] = wp[(size_t)i * DM_N];
    }

    for (int k0 = 0; k0 < DM_N; k0 += 32) {
        __syncthreads();
#pragma unroll
        for (int u = 0; u < 4; u++) {
            int fid = u * 256 + tid;
            int r = fid >> 3, c4 = fid & 7;
            float4 v = xf[u];
            v.x = f2tff(v.x); v.y = f2tff(v.y); v.z = f2tff(v.z); v.w = f2tff(v.w);
            *(float4*)&Xs[r * 36 + 4 * c4] = v;
            int n = fid & 127, c = fid >> 7;
            float4 w4 = make_float4(f2tff(wf[u][0]), f2tff(wf[u][1]),
                                    f2tff(wf[u][2]), f2tff(wf[u][3]));
            *(float4*)&Ws[n * 32 + 4 * (c ^ (n & 7))] = w4;
        }
        __syncthreads();
        if (k0 + 32 < DM_N) {
#pragma unroll
            for (int u = 0; u < 4; u++) {
                int fid = u * 256 + tid;
                int r = fid >> 3, c4 = fid & 7;
                xf[u] = *(const float4*)(X + (size_t)(m0 + r) * DM_N + k0 + 32 + 4 * c4);
                int n = fid & 127, c = fid >> 7;
                const float* wp = W + (size_t)(k0 + 32 + 4 * c) * DM_N + n0 + n;
#pragma unroll
                for (int i = 0; i < 4; i++) wf[u][i] = wp[(size_t)i * DM_N];
            }
        }
#pragma unroll
        for (int ks = 0; ks < 4; ks++) {
            const int kk = ks * 8;
            unsigned a[4][4], b[4][2];
#pragma unroll
            for (int mi = 0; mi < 4; mi++) {
                unsigned ad = sptr(&Xs[(wm * 64 + mi * 16 + (lane & 15)) * 36
                                       + kk + 4 * (lane >> 4)]);
                ldsm4(a[mi][0], a[mi][1], a[mi][2], a[mi][3], ad);
            }
#pragma unroll
            for (int p = 0; p < 2; p++) {
                int r  = wn * 32 + p * 16 + ((lane & 16) ? 8 : 0) + (lane & 7);
                int cc = (kk >> 2) + ((lane >> 3) & 1);
                unsigned ad = sptr(&Ws[r * 32 + 4 * (cc ^ (r & 7))]);
                unsigned t0, t1, t2, t3;
                ldsm4(t0, t1, t2, t3, ad);
                b[2 * p][0] = t0; b[2 * p][1] = t1;
                b[2 * p + 1][0] = t2; b[2 * p + 1][1] = t3;
            }
#pragma unroll
            for (int mi = 0; mi < 4; mi++)
#pragma unroll
                for (int nj = 0; nj < 4; nj++)
                    mma8(acc[mi][nj], a[mi], b[nj]);
        }
    }

#pragma unroll
    for (int mi = 0; mi < 4; mi++) {
#pragma unroll
        for (int nj = 0; nj < 4; nj++) {
            int row = m0 + wm * 64 + mi * 16 + (lane >> 2);
            int col = n0 + wn * 32 + nj * 8 + 2 * (lane & 3);
            float b0v = bias[col], b1v = bias[col + 1];
            float2 v0 = make_float2(acc[mi][nj][0] + b0v, acc[mi][nj][1] + b1v);
            float2 v1 = make_float2(acc[mi][nj][2] + b0v, acc[mi][nj][3] + b1v);
            if (HL) {
                int h = col >> 6, d = col & 63;
                int bi = row >> 11, s = row & (S_N - 1);
                size_t base = (((size_t)(bi * H_N + h)) * S_N + s) * 64 + d;
                *(float2*)(out + base) = v0;
                *(float2*)(out + base + (size_t)8 * 64) = v1;
            } else {
                float* p = out + (size_t)row * DM_N + col;
                *(float2*)p = v0;
                *(float2*)(p + (size_t)8 * DM_N) = v1;
            }
        }
    }
}

// ---------------------------------------------------------------------------
// Flash attention, tf32 tensor cores.
// CTA = (b,h) x 256 q rows, 8 warps, each warp 32 rows (2 x m16 blocks).
// 64-key tiles. P never touches smem: C-frag -> A-frag via quad shuffles.
// Qs[256][68] (pre-scaled by 1/8), Ks[64][68] natural, Vt[64 d][68 key].
// ---------------------------------------------------------------------------
#define QROWS 256
#define ATTN_SMEM_BYTES ((QROWS + 64 + 64) * 68 * 4)

__global__ __launch_bounds__(256)
void attn_tc(const float* __restrict__ Q, const float* __restrict__ K,
             const float* __restrict__ V, float* __restrict__ O)
{
    extern __shared__ __align__(16) float sm[];
    float* Qs = sm;                    // 256*68
    float* Ks = Qs + QROWS * 68;       // 64*68
    float* Vt = Ks + 64 * 68;          // 64*68

    const int tid  = threadIdx.x;
    const int lane = tid & 31;
    const int wid  = tid >> 5;
    const int bh   = blockIdx.y;
    const int q0   = blockIdx.x * QROWS;

    const float* Qb = Q + ((size_t)bh * S_N + q0) * 64;
    const float* Kb = K + (size_t)bh * S_N * 64;
    const float* Vb = V + (size_t)bh * S_N * 64;

    // load Q once, pre-scaled by 1/sqrt(64) (exact exponent shift), tf32-rounded
#pragma unroll
    for (int u = 0; u < 16; u++) {
        int fid = u * 256 + tid;
        int r = fid >> 4, c4 = fid & 15;
        float4 v = *(const float4*)(Qb + (size_t)r * 64 + 4 * c4);
        v.x = f2tff(v.x * 0.125f); v.y = f2tff(v.y * 0.125f);
        v.z = f2tff(v.z * 0.125f); v.w = f2tff(v.w * 0.125f);
        *(float4*)&Qs[r * 68 + 4 * c4] = v;
    }

    float accO[2][8][4];
#pragma unroll
    for (int mi = 0; mi < 2; mi++)
#pragma unroll
        for (int j = 0; j < 8; j++)
#pragma unroll
            for (int r = 0; r < 4; r++) accO[mi][j][r] = 0.f;
    float mst[2][2] = {{-INFINITY, -INFINITY}, {-INFINITY, -INFINITY}};
    float lst[2][2] = {{0.f, 0.f}, {0.f, 0.f}};

    // shuffle sources for P re-fragmentation (intra-quad permutation)
    const int tq = lane & 3;
    const int s1 = (lane & 28) | (tq >> 1);
    const int s2 = s1 + 2;
    const bool todd = (tq & 1);

    float4 kf[4], vf[4];
#pragma unroll
    for (int u = 0; u < 4; u++) {
        int fid = u * 256 + tid;
        { int r = fid >> 4, c4 = fid & 15;
          kf[u] = *(const float4*)(Kb + (size_t)r * 64 + 4 * c4); }
        { int key = fid & 63, c4 = fid >> 6;
          vf[u] = *(const float4*)(Vb + (size_t)key * 64 + 4 * c4); }
    }

    for (int kt = 0; kt < S_N / 64; kt++) {
        __syncthreads();
#pragma unroll
        for (int u = 0; u < 4; u++) {
            int fid = u * 256 + tid;
            { int r = fid >> 4, c4 = fid & 15;
              float4 v = kf[u];
              v.x = f2tff(v.x); v.y = f2tff(v.y); v.z = f2tff(v.z); v.w = f2tff(v.w);
              *(float4*)&Ks[r * 68 + 4 * c4] = v; }
            { int key = fid & 63, c4 = fid >> 6;
              float4 v = vf[u];
              Vt[(4 * c4 + 0) * 68 + key] = f2tff(v.x);
              Vt[(4 * c4 + 1) * 68 + key] = f2tff(v.y);
              Vt[(4 * c4 + 2) * 68 + key] = f2tff(v.z);
              Vt[(4 * c4 + 3) * 68 + key] = f2tff(v.w); }
        }
        __syncthreads();
        if (kt + 1 < S_N / 64) {
            const float* Kb2 = Kb + (size_t)(kt + 1) * 64 * 64;
            const float* Vb2 = Vb + (size_t)(kt + 1) * 64 * 64;
#pragma unroll
            for (int u = 0; u < 4; u++) {
                int fid = u * 256 + tid;
                { int r = fid >> 4, c4 = fid & 15;
                  kf[u] = *(const float4*)(Kb2 + (size_t)r * 64 + 4 * c4); }
                { int key = fid & 63, c4 = fid >> 6;
                  vf[u] = *(const float4*)(Vb2 + (size_t)key * 64 + 4 * c4); }
            }
        }

        // ---- S = (Q/8) @ K^T ----
        float accS[2][8][4];
#pragma unroll
        for (int mi = 0; mi < 2; mi++)
#pragma unroll
            for (int j = 0; j < 8; j++)
#pragma unroll
                for (int r = 0; r < 4; r++) accS[mi][j][r] = 0.f;
#pragma unroll
        for (int ks = 0; ks < 8; ks++) {
            const int kk = ks * 8;
            unsigned a[2][4];
#pragma unroll
            for (int mi = 0; mi < 2; mi++) {
                unsigned ad = sptr(&Qs[(wid * 32 + mi * 16 + (lane & 15)) * 68
                                       + kk + 4 * (lane >> 4)]);
                ldsm4(a[mi][0], a[mi][1], a[mi][2], a[mi][3], ad);
            }
#pragma unroll
            for (int p = 0; p < 4; p++) {
                int r = p * 16 + ((lane & 16) ? 8 : 0) + (lane & 7);
                unsigned ad = sptr(&Ks[r * 68 + kk + 4 * ((lane >> 3) & 1)]);
                unsigned t0, t1, t2, t3;
                ldsm4(t0, t1, t2, t3, ad);
                unsigned b0[2] = {t0, t1}, b1[2] = {t2, t3};
                mma8(accS[0][2 * p], a[0], b0);
                mma8(accS[0][2 * p + 1], a[0], b1);
                mma8(accS[1][2 * p], a[1], b0);
                mma8(accS[1][2 * p + 1], a[1], b1);
            }
        }

        // ---- online softmax (registers + quad shuffles only) ----
#pragma unroll
        for (int mi = 0; mi < 2; mi++) {
            float r0 = -INFINITY, r1 = -INFINITY;
#pragma unroll
            for (int j = 0; j < 8; j++) {
                r0 = fmaxf(r0, fmaxf(accS[mi][j][0], accS[mi][j][1]));
                r1 = fmaxf(r1, fmaxf(accS[mi][j][2], accS[mi][j][3]));
            }
            r0 = fmaxf(r0, __shfl_xor_sync(0xffffffffu, r0, 1));
            r0 = fmaxf(r0, __shfl_xor_sync(0xffffffffu, r0, 2));
            r1 = fmaxf(r1, __shfl_xor_sync(0xffffffffu, r1, 1));
            r1 = fmaxf(r1, __shfl_xor_sync(0xffffffffu, r1, 2));
            float mn0 = fmaxf(mst[mi][0], r0), mn1 = fmaxf(mst[mi][1], r1);
            float al0 = __expf(mst[mi][0] - mn0), al1 = __expf(mst[mi][1] - mn1);
            mst[mi][0] = mn0; mst[mi][1] = mn1;
            float sm0 = 0.f, sm1 = 0.f;
#pragma unroll
            for (int j = 0; j < 8; j++) {
                accS[mi][j][0] = __expf(accS[mi][j][0] - mn0);
                accS[mi][j][1] = __expf(accS[mi][j][1] - mn0);
                accS[mi][j][2] = __expf(accS[mi][j][2] - mn1);
                accS[mi][j][3] = __expf(accS[mi][j][3] - mn1);
                sm0 += accS[mi][j][0] + accS[mi][j][1];
                sm1 += accS[mi][j][2] + accS[mi][j][3];
            }
            sm0 += __shfl_xor_sync(0xffffffffu, sm0, 1);
            sm0 += __shfl_xor_sync(0xffffffffu, sm0, 2);
            sm1 += __shfl_xor_sync(0xffffffffu, sm1, 1);
            sm1 += __shfl_xor_sync(0xffffffffu, sm1, 2);
            lst[mi][0] = lst[mi][0] * al0 + sm0;
            lst[mi][1] = lst[mi][1] * al1 + sm1;
#pragma unroll
            for (int j = 0; j < 8; j++) {
                accO[mi][j][0] *= al0; accO[mi][j][1] *= al0;
                accO[mi][j][2] *= al1; accO[mi][j][3] *= al1;
            }
        }

        // ---- O += P @ V : P re-fragmented C->A via shuffles, V from Vt ----
#pragma unroll
        for (int ks = 0; ks < 8; ks++) {
            unsigned a[2][4];
#pragma unroll
            for (int mi = 0; mi < 2; mi++) {
                float p0 = f2tff(accS[mi][ks][0]);
                float p1 = f2tff(accS[mi][ks][1]);
                float p2 = f2tff(accS[mi][ks][2]);
                float p3 = f2tff(accS[mi][ks][3]);
                float u0 = __shfl_sync(0xffffffffu, p0, s1);
                float u1 = __shfl_sync(0xffffffffu, p1, s1);
                float v0 = __shfl_sync(0xffffffffu, p0, s2);
                float v1 = __shfl_sync(0xffffffffu, p1, s2);
                a[mi][0] = __float_as_uint(todd ? u1 : u0);
                a[mi][2] = __float_as_uint(todd ? v1 : v0);
                float u2 = __shfl_sync(0xffffffffu, p2, s1);
                float u3 = __shfl_sync(0xffffffffu, p3, s1);
                float v2 = __shfl_sync(0xffffffffu, p2, s2);
                float v3 = __shfl_sync(0xffffffffu, p3, s2);
                a[mi][1] = __float_as_uint(todd ? u3 : u2);
                a[mi][3] = __float_as_uint(todd ? v3 : v2);
            }
            const int kk = ks * 8;
#pragma unroll
            for (int p = 0; p < 4; p++) {
                int r = p * 16 + ((lane & 16) ? 8 : 0) + (lane & 7);
                unsigned ad = sptr(&Vt[r * 68 + kk + 4 * ((lane >> 3) & 1)]);
                unsigned t0, t1, t2, t3;
                ldsm4(t0, t1, t2, t3, ad);
                unsigned b0[2] = {t0, t1}, b1[2] = {t2, t3};
                mma8(accO[0][2 * p], a[0], b0);
                mma8(accO[0][2 * p + 1], a[0], b1);
                mma8(accO[1][2 * p], a[1], b0);
                mma8(accO[1][2 * p + 1], a[1], b1);
            }
        }
    }

    // epilogue: normalize, write [B,S,1024] at head offset
    const int b = bh >> 4, h = bh & 15;
#pragma unroll
    for (int mi = 0; mi < 2; mi++) {
        const float inv0 = 1.f / lst[mi][0], inv1 = 1.f / lst[mi][1];
        const int r0 = q0 + wid * 32 + mi * 16 + (lane >> 2);
#pragma unroll
        for (int j = 0; j < 8; j++) {
            int col = h * 64 + j * 8 + 2 * (lane & 3);
            float* p = O + ((size_t)b * S_N + r0) * DM_N + col;
            *(float2*)p = make_float2(accO[mi][j][0] * inv0, accO[mi][j][1] * inv0);
            *(float2*)(p + (size_t)8 * DM_N) =
                make_float2(accO[mi][j][2] * inv1, accO[mi][j][3] * inv1);
        }
    }
}

// ---------------------------------------------------------------------------
// Launch
// ---------------------------------------------------------------------------
extern "C" void kernel_launch(void* const* d_in, const int* in_sizes, int n_in,
                              void* d_out, int out_size)
{
    const float* v  = (const float*)d_in[0];
    const float* k  = (const float*)d_in[1];
    const float* q  = (const float*)d_in[2];
    const float* wq = (const float*)d_in[3];
    const float* bq = (const float*)d_in[4];
    const float* wk = (const float*)d_in[5];
    const float* bk = (const float*)d_in[6];
    const float* wv = (const float*)d_in[7];
    const float* bv = (const float*)d_in[8];
    const float* wo = (const float*)d_in[9];
    const float* bo = (const float*)d_in[10];
    float* out = (float*)d_out;

    float *pQ, *pK, *pV, *pA;
    cudaGetSymbolAddress((void**)&pQ, g_Q);
    cudaGetSymbolAddress((void**)&pK, g_K);
    cudaGetSymbolAddress((void**)&pV, g_V);
    cudaGetSymbolAddress((void**)&pA, g_A);

    cudaFuncSetAttribute(attn_tc,
                         cudaFuncAttributeMaxDynamicSharedMemorySize,
                         ATTN_SMEM_BYTES);

    dim3 gg(DM_N / 128, M_N / 128);   // (8, 64)
    gemm_tc<true><<<gg, 256>>>(q, wq, bq, pQ);
    gemm_tc<true><<<gg, 256>>>(k, wk, bk, pK);
    gemm_tc<true><<<gg, 256>>>(v, wv, bv, pV);

    attn_tc<<<dim3(S_N / QROWS, B_N * H_N), 256, ATTN_SMEM_BYTES>>>(pQ, pK, pV, pA);

    gemm_tc<false><<<gg, 256>>>(pA, wo, bo, out);
}